// round 3
// baseline (speedup 1.0000x reference)
#include <cuda_runtime.h>
#include <cuda_bf16.h>
#include <cstdint>
#include <math.h>

#define L_DIM 1024
#define B_DIM 32
#define D_DIM 1024
#define M_DIM (L_DIM*B_DIM)   // 32768
#define N_DIM (3*D_DIM)       // 3072
#define K_DIM D_DIM           // 1024

// Scratch (device globals: allocation-free rule)
__device__ __align__(16) float g_u0[(size_t)M_DIM*D_DIM];
__device__ __align__(16) float g_g1[(size_t)M_DIM*D_DIM];
__device__ __align__(16) float g_g2[(size_t)M_DIM*D_DIM];
__device__ __align__(16) __nv_bfloat16 g_Wh[(size_t)N_DIM*K_DIM];  // W^T hi, row n'=j*1024+d
__device__ __align__(16) __nv_bfloat16 g_Wl[(size_t)N_DIM*K_DIM];  // W^T lo
__device__ __align__(16) __nv_bfloat16 g_Xh[(size_t)M_DIM*K_DIM];  // x hi
__device__ __align__(16) __nv_bfloat16 g_Xl[(size_t)M_DIM*K_DIM];  // x lo

// ---------------- helpers ----------------
__device__ __forceinline__ uint32_t smem_u32(const void* p) {
    uint32_t a;
    asm("{ .reg .u64 t; cvta.to.shared.u64 t, %1; cvt.u32.u64 %0, t; }" : "=r"(a) : "l"(p));
    return a;
}
__device__ __forceinline__ void cp16(uint32_t s, const void* g) {
    asm volatile("cp.async.cg.shared.global [%0], [%1], 16;" :: "r"(s), "l"(g) : "memory");
}
__device__ __forceinline__ void cp_commit() { asm volatile("cp.async.commit_group;" ::: "memory"); }
template<int N> __device__ __forceinline__ void cp_wait() {
    asm volatile("cp.async.wait_group %0;" :: "n"(N) : "memory");
}
__device__ __forceinline__ void ldmx4(uint32_t* r, uint32_t a) {
    asm volatile("ldmatrix.sync.aligned.m8n8.x4.shared.b16 {%0,%1,%2,%3}, [%4];"
                 : "=r"(r[0]), "=r"(r[1]), "=r"(r[2]), "=r"(r[3]) : "r"(a));
}
__device__ __forceinline__ void mma16816(float* c, const uint32_t* a, uint32_t b0, uint32_t b1) {
    asm volatile("mma.sync.aligned.m16n8k16.row.col.f32.bf16.bf16.f32 "
                 "{%0,%1,%2,%3}, {%4,%5,%6,%7}, {%8,%9}, {%0,%1,%2,%3};"
                 : "+f"(c[0]), "+f"(c[1]), "+f"(c[2]), "+f"(c[3])
                 : "r"(a[0]), "r"(a[1]), "r"(a[2]), "r"(a[3]), "r"(b0), "r"(b1));
}
__device__ __forceinline__ uint32_t pack_bf2(float a, float b) {
    __nv_bfloat162 t = __floats2bfloat162_rn(a, b);
    return *reinterpret_cast<uint32_t*>(&t);
}
__device__ __forceinline__ uint32_t sw(uint32_t off) { return off ^ ((off >> 3) & 0x70); }

// ---------------- prep W: W[k][n] -> Wt[n'][k] hi/lo bf16, n'=(n%3)*1024+(n/3)
__global__ void __launch_bounds__(256) prepw_kernel(const float* __restrict__ W) {
    __shared__ float t[32][33];
    const int n0 = blockIdx.x * 32, k0 = blockIdx.y * 32;
    const int x = threadIdx.x, y = threadIdx.y;  // 32 x 8
#pragma unroll
    for (int i = 0; i < 4; i++)
        t[y + 8*i][x] = W[(size_t)(k0 + y + 8*i) * N_DIM + n0 + x];
    __syncthreads();
#pragma unroll
    for (int i = 0; i < 4; i++) {
        int nl = y + 8*i, n = n0 + nl;
        int np = (n % 3) * 1024 + n / 3;
        float v  = t[x][nl];
        __nv_bfloat16 h = __float2bfloat16(v);
        g_Wh[(size_t)np * K_DIM + k0 + x] = h;
        g_Wl[(size_t)np * K_DIM + k0 + x] = __float2bfloat16(v - __bfloat162float(h));
    }
}

// ---------------- prep X: split x fp32 -> hi/lo bf16
__global__ void __launch_bounds__(256) prepx_kernel(const float* __restrict__ x) {
    size_t i = ((size_t)blockIdx.x * 256 + threadIdx.x) * 4;
    float4 v = *(const float4*)(x + i);
    float h0 = __bfloat162float(__float2bfloat16(v.x));
    float h1 = __bfloat162float(__float2bfloat16(v.y));
    float h2 = __bfloat162float(__float2bfloat16(v.z));
    float h3 = __bfloat162float(__float2bfloat16(v.w));
    *(uint2*)(g_Xh + i) = make_uint2(pack_bf2(h0, h1), pack_bf2(h2, h3));
    *(uint2*)(g_Xl + i) = make_uint2(pack_bf2(v.x-h0, v.y-h1), pack_bf2(v.z-h2, v.w-h3));
}

// ---------------- GEMM: U[m][n'] = X @ Wt^T, mma.sync bf16 3-pass
#define BM 128
#define BN 128
#define KC 64
#define NCHUNK (K_DIM/KC)          // 16
#define TILE_B 16384               // 128 rows x 128B
#define STAGE_B (4*TILE_B)         // Ah, Al, Bh, Bl
#define GEMM_SMEM (3*STAGE_B)      // 196608

__device__ __forceinline__ void load_stage(uint32_t sbase, int bm, int bn, int k0, int tid) {
    const __nv_bfloat16* srcs[4] = {
        g_Xh + (size_t)bm * K_DIM + k0, g_Xl + (size_t)bm * K_DIM + k0,
        g_Wh + (size_t)bn * K_DIM + k0, g_Wl + (size_t)bn * K_DIM + k0 };
#pragma unroll
    for (int t = 0; t < 4; t++) {
#pragma unroll
        for (int p = 0; p < 4; p++) {
            int idx = tid + p * 256;
            int row = idx >> 3, ch = idx & 7;
            cp16(sbase + t * TILE_B + sw(row * 128 + ch * 16),
                 srcs[t] + (size_t)row * K_DIM + ch * 8);
        }
    }
}

__global__ void __launch_bounds__(256, 1)
gemm_kernel(const float* __restrict__ bias) {
    extern __shared__ char smem[];
    const uint32_t sb = smem_u32(smem);
    const int tid = threadIdx.x, lane = tid & 31, wid = tid >> 5;
    const int wm = (wid & 3) * 32, wn = (wid >> 2) * 64;
    const int bn = blockIdx.x * BN, bm = blockIdx.y * BM;

    float acc[2][8][4];
#pragma unroll
    for (int a = 0; a < 2; a++)
#pragma unroll
        for (int b = 0; b < 8; b++)
#pragma unroll
            for (int c = 0; c < 4; c++) acc[a][b][c] = 0.f;

    load_stage(sb, bm, bn, 0, tid);  cp_commit();
    load_stage(sb + STAGE_B, bm, bn, KC, tid);  cp_commit();

    // precomputed swizzled fragment offsets (within a tile)
    uint32_t a_off[2], b_off[4];
#pragma unroll
    for (int mt = 0; mt < 2; mt++)
        a_off[mt] = sw((uint32_t)((wm + mt*16 + (lane & 15)) * 128 + (lane >> 4) * 16));
#pragma unroll
    for (int nt = 0; nt < 4; nt++)
        b_off[nt] = sw((uint32_t)((wn + nt*16 + ((lane >> 4) << 3) + (lane & 7)) * 128
                                  + ((lane >> 3) & 1) * 16));

    for (int chk = 0; chk < NCHUNK; chk++) {
        if (chk < NCHUNK - 2) cp_wait<1>(); else cp_wait<0>();
        __syncthreads();
        if (chk + 2 < NCHUNK) {
            load_stage(sb + ((chk + 2) % 3) * STAGE_B, bm, bn, (chk + 2) * KC, tid);
            cp_commit();
        }
        const uint32_t stg = sb + (chk % 3) * STAGE_B;
#pragma unroll
        for (int s = 0; s < 4; s++) {
            const uint32_t ks = (uint32_t)(s * 32);
            uint32_t ah[2][4], al[2][4], bh[4][4], bl[4][4];
#pragma unroll
            for (int mt = 0; mt < 2; mt++) {
                ldmx4(ah[mt], stg + 0*TILE_B + sw((a_off[mt] ^ ((a_off[mt]>>3)&0x70)) + 0) );
            }
            // note: a_off already swizzled; add ks to the *unswizzled* column ->
            // recompute properly below (ks lands in bits [5:6] of column, interacts with swizzle)
#pragma unroll
            for (int mt = 0; mt < 2; mt++) {
                uint32_t off = (uint32_t)((wm + mt*16 + (lane & 15)) * 128 + ks + (lane >> 4) * 16);
                ldmx4(ah[mt], stg + 0*TILE_B + sw(off));
                ldmx4(al[mt], stg + 1*TILE_B + sw(off));
            }
#pragma unroll
            for (int nt = 0; nt < 4; nt++) {
                uint32_t off = (uint32_t)((wn + nt*16 + ((lane >> 4) << 3) + (lane & 7)) * 128
                                          + ks + ((lane >> 3) & 1) * 16);
                ldmx4(bh[nt], stg + 2*TILE_B + sw(off));
                ldmx4(bl[nt], stg + 3*TILE_B + sw(off));
            }
#pragma unroll
            for (int mt = 0; mt < 2; mt++)
#pragma unroll
                for (int n8 = 0; n8 < 8; n8++) {
                    const int nt = n8 >> 1, hf = (n8 & 1) * 2;
                    mma16816(acc[mt][n8], ah[mt], bh[nt][hf], bh[nt][hf+1]);
                    mma16816(acc[mt][n8], ah[mt], bl[nt][hf], bl[nt][hf+1]);
                    mma16816(acc[mt][n8], al[mt], bh[nt][hf], bh[nt][hf+1]);
                }
        }
    }

    // Epilogue: direct stores, sigmoid+bias fused for j=1,2
    const int j = blockIdx.x >> 3;            // n' = j*1024 + d
    float* dst = (j == 0) ? g_u0 : (j == 1) ? g_g1 : g_g2;
    const int dl0 = (blockIdx.x & 7) * 128;
    const int r0 = bm + wm + (lane >> 2);
#pragma unroll
    for (int mt = 0; mt < 2; mt++) {
#pragma unroll
        for (int n8 = 0; n8 < 8; n8++) {
            const int col = dl0 + wn + n8 * 8 + (lane & 3) * 2;
            float b0 = 0.f, b1 = 0.f;
            if (j) { b0 = bias[(j-1)*1024 + col]; b1 = bias[(j-1)*1024 + col + 1]; }
            float v0 = acc[mt][n8][0], v1 = acc[mt][n8][1];
            float v2 = acc[mt][n8][2], v3 = acc[mt][n8][3];
            if (j) {
                v0 = 1.f / (1.f + __expf(-(v0 + b0)));
                v1 = 1.f / (1.f + __expf(-(v1 + b1)));
                v2 = 1.f / (1.f + __expf(-(v2 + b0)));
                v3 = 1.f / (1.f + __expf(-(v3 + b1)));
            }
            *(float2*)&dst[(size_t)(r0 + mt*16) * 1024 + col]     = make_float2(v0, v1);
            *(float2*)&dst[(size_t)(r0 + mt*16 + 8) * 1024 + col] = make_float2(v2, v3);
        }
    }
}

// ---------------- scan: c_l = (c - u0)*g1 + u0 ; h = (tanh(c)-x)*g2 + x
__global__ void __launch_bounds__(256) scan_kernel(const float* __restrict__ x,
                                                   const float* __restrict__ c0,
                                                   float* __restrict__ h) {
    const int b = blockIdx.x >> 2;
    const int d = ((blockIdx.x & 3) << 8) + threadIdx.x;
    const size_t STEP = (size_t)B_DIM * D_DIM;     // 32768
    size_t off = (size_t)b * D_DIM + d;
    float c = c0[off];
    float cu[4], cg[4], ce[4], cx[4];
#pragma unroll
    for (int i = 0; i < 4; i++) {
        size_t o = off + i*STEP;
        cu[i] = g_u0[o]; cg[i] = g_g1[o]; ce[i] = g_g2[o]; cx[i] = x[o];
    }
#pragma unroll 1
    for (int g = 0; g < 256; g++) {
        float nu[4], ng[4], ne[4], nx[4];
        if (g < 255) {
            size_t o2 = off + 4*STEP;
#pragma unroll
            for (int i = 0; i < 4; i++) {
                size_t o = o2 + i*STEP;
                nu[i] = g_u0[o]; ng[i] = g_g1[o]; ne[i] = g_g2[o]; nx[i] = x[o];
            }
        }
#pragma unroll
        for (int i = 0; i < 4; i++) {
            c = (c - cu[i]) * cg[i] + cu[i];
            // tanh via exp: error ~1e-6
            float e = __expf(-2.f * c);
            float th = (1.f - e) / (1.f + e);
            h[off + i*STEP] = (th - cx[i]) * ce[i] + cx[i];
        }
        off += 4*STEP;
#pragma unroll
        for (int i = 0; i < 4; i++) { cu[i]=nu[i]; cg[i]=ng[i]; ce[i]=ne[i]; cx[i]=nx[i]; }
    }
}

// ---------------- launch ----------------
extern "C" void kernel_launch(void* const* d_in, const int* in_sizes, int n_in,
                              void* d_out, int out_size) {
    const float* x    = (const float*)d_in[0];
    const float* W    = (const float*)d_in[1];
    const float* bias = (const float*)d_in[2];
    const float* c0   = (const float*)d_in[3];
    float* out = (float*)d_out;

    static int smem_set = 0;
    if (!smem_set) {
        cudaFuncSetAttribute(gemm_kernel, cudaFuncAttributeMaxDynamicSharedMemorySize, GEMM_SMEM);
        smem_set = 1;
    }

    prepw_kernel<<<dim3(N_DIM/32, K_DIM/32), dim3(32, 8)>>>(W);
    prepx_kernel<<<(M_DIM*(size_t)K_DIM)/1024, 256>>>(x);
    gemm_kernel<<<dim3(N_DIM/BN, M_DIM/BM), 256, GEMM_SMEM>>>(bias);
    scan_kernel<<<(B_DIM*D_DIM)/256, 256>>>(x, c0, out);
}

// round 4
// speedup vs baseline: 2.1203x; 2.1203x over previous
#include <cuda_runtime.h>
#include <cuda_fp16.h>
#include <cstdint>
#include <math.h>

#define L_DIM 1024
#define B_DIM 32
#define D_DIM 1024
#define M_DIM (L_DIM*B_DIM)   // 32768
#define N_DIM (3*D_DIM)       // 3072
#define K_DIM D_DIM           // 1024

// Scratch (device globals: allocation-free rule)
__device__ __align__(16) float g_u0[(size_t)M_DIM*D_DIM];
__device__ __align__(16) float g_g1[(size_t)M_DIM*D_DIM];
__device__ __align__(16) float g_g2[(size_t)M_DIM*D_DIM];
__device__ __align__(16) __half g_Wf[(size_t)N_DIM*K_DIM];  // W^T fp16, row n'=j*1024+d
__device__ __align__(16) __half g_Xf[(size_t)M_DIM*K_DIM];  // x fp16

// ---------------- helpers ----------------
__device__ __forceinline__ uint32_t smem_u32(const void* p) {
    uint32_t a;
    asm("{ .reg .u64 t; cvta.to.shared.u64 t, %1; cvt.u32.u64 %0, t; }" : "=r"(a) : "l"(p));
    return a;
}
__device__ __forceinline__ void cp16(uint32_t s, const void* g) {
    asm volatile("cp.async.cg.shared.global [%0], [%1], 16;" :: "r"(s), "l"(g) : "memory");
}
__device__ __forceinline__ void cp_commit() { asm volatile("cp.async.commit_group;" ::: "memory"); }
template<int N> __device__ __forceinline__ void cp_wait() {
    asm volatile("cp.async.wait_group %0;" :: "n"(N) : "memory");
}
__device__ __forceinline__ void ldmx4(uint32_t* r, uint32_t a) {
    asm volatile("ldmatrix.sync.aligned.m8n8.x4.shared.b16 {%0,%1,%2,%3}, [%4];"
                 : "=r"(r[0]), "=r"(r[1]), "=r"(r[2]), "=r"(r[3]) : "r"(a));
}
__device__ __forceinline__ void mma16816(float* c, const uint32_t* a, uint32_t b0, uint32_t b1) {
    asm volatile("mma.sync.aligned.m16n8k16.row.col.f32.f16.f16.f32 "
                 "{%0,%1,%2,%3}, {%4,%5,%6,%7}, {%8,%9}, {%0,%1,%2,%3};"
                 : "+f"(c[0]), "+f"(c[1]), "+f"(c[2]), "+f"(c[3])
                 : "r"(a[0]), "r"(a[1]), "r"(a[2]), "r"(a[3]), "r"(b0), "r"(b1));
}
__device__ __forceinline__ uint32_t sw(uint32_t off) { return off ^ ((off >> 3) & 0x70); }
__device__ __forceinline__ uint32_t pack_h2(float a, float b) {
    __half2 t = __floats2half2_rn(a, b);
    return *reinterpret_cast<uint32_t*>(&t);
}

// ---------------- prep W: W[k][n] -> Wt[n'][k] fp16, n'=(n%3)*1024+(n/3)
__global__ void __launch_bounds__(256) prepw_kernel(const float* __restrict__ W) {
    __shared__ float t[32][33];
    const int n0 = blockIdx.x * 32, k0 = blockIdx.y * 32;
    const int x = threadIdx.x, y = threadIdx.y;  // 32 x 8
#pragma unroll
    for (int i = 0; i < 4; i++)
        t[y + 8*i][x] = W[(size_t)(k0 + y + 8*i) * N_DIM + n0 + x];
    __syncthreads();
#pragma unroll
    for (int i = 0; i < 4; i++) {
        int nl = y + 8*i, n = n0 + nl;
        int np = (n % 3) * 1024 + n / 3;
        g_Wf[(size_t)np * K_DIM + k0 + x] = __float2half_rn(t[x][nl]);
    }
}

// ---------------- prep X: x fp32 -> fp16
__global__ void __launch_bounds__(256) prepx_kernel(const float* __restrict__ x) {
    size_t i = ((size_t)blockIdx.x * 256 + threadIdx.x) * 8;
    float4 v0 = *(const float4*)(x + i);
    float4 v1 = *(const float4*)(x + i + 4);
    uint4 o;
    o.x = pack_h2(v0.x, v0.y); o.y = pack_h2(v0.z, v0.w);
    o.z = pack_h2(v1.x, v1.y); o.w = pack_h2(v1.z, v1.w);
    *(uint4*)(g_Xf + i) = o;
}

// ---------------- GEMM: U[m][n'] = X @ Wt^T, mma.sync fp16 single-pass
#define BM 128
#define BN 128
#define KC 64
#define NCHUNK (K_DIM/KC)          // 16
#define TILE_B 16384               // 128 rows x 128B
#define STAGE_B (2*TILE_B)         // A, B
#define NSTG 4
#define GEMM_SMEM (NSTG*STAGE_B)   // 131072

__device__ __forceinline__ void load_stage(uint32_t sbase, int bm, int bn, int k0, int tid) {
    const __half* srcs[2] = { g_Xf + (size_t)bm * K_DIM + k0,
                              g_Wf + (size_t)bn * K_DIM + k0 };
#pragma unroll
    for (int t = 0; t < 2; t++) {
#pragma unroll
        for (int p = 0; p < 4; p++) {
            int idx = tid + p * 256;
            int row = idx >> 3, ch = idx & 7;
            cp16(sbase + t * TILE_B + sw(row * 128 + ch * 16),
                 srcs[t] + (size_t)row * K_DIM + ch * 8);
        }
    }
}

__global__ void __launch_bounds__(256, 1)
gemm_kernel(const float* __restrict__ bias) {
    extern __shared__ char smem[];
    const uint32_t sb = smem_u32(smem);
    const int tid = threadIdx.x, lane = tid & 31, wid = tid >> 5;
    const int wm = (wid & 3) * 32, wn = (wid >> 2) * 64;
    const int bn = blockIdx.x * BN, bm = blockIdx.y * BM;

    float acc[2][8][4];
#pragma unroll
    for (int a = 0; a < 2; a++)
#pragma unroll
        for (int b = 0; b < 8; b++)
#pragma unroll
            for (int c = 0; c < 4; c++) acc[a][b][c] = 0.f;

    load_stage(sb,             bm, bn, 0,    tid); cp_commit();
    load_stage(sb +   STAGE_B, bm, bn, KC,   tid); cp_commit();
    load_stage(sb + 2*STAGE_B, bm, bn, 2*KC, tid); cp_commit();

    for (int chk = 0; chk < NCHUNK; chk++) {
        cp_wait<2>();
        __syncthreads();
        if (chk + 3 < NCHUNK) {
            load_stage(sb + ((chk + 3) & 3) * STAGE_B, bm, bn, (chk + 3) * KC, tid);
            cp_commit();
        }
        const uint32_t stg = sb + (chk & 3) * STAGE_B;
#pragma unroll
        for (int s = 0; s < 4; s++) {
            const uint32_t ks = (uint32_t)(s * 32);
            uint32_t ah[2][4], bh[4][4];
#pragma unroll
            for (int mt = 0; mt < 2; mt++) {
                uint32_t off = (uint32_t)((wm + mt*16 + (lane & 15)) * 128 + ks + (lane >> 4) * 16);
                ldmx4(ah[mt], stg + sw(off));
            }
#pragma unroll
            for (int nt = 0; nt < 4; nt++) {
                uint32_t off = (uint32_t)((wn + nt*16 + ((lane >> 4) << 3) + (lane & 7)) * 128
                                          + ks + ((lane >> 3) & 1) * 16);
                ldmx4(bh[nt], stg + TILE_B + sw(off));
            }
#pragma unroll
            for (int mt = 0; mt < 2; mt++)
#pragma unroll
                for (int n8 = 0; n8 < 8; n8++) {
                    const int nt = n8 >> 1, hf = (n8 & 1) * 2;
                    mma16816(acc[mt][n8], ah[mt], bh[nt][hf], bh[nt][hf+1]);
                }
        }
    }

    // Epilogue: direct stores, sigmoid+bias fused for j=1,2
    const int j = blockIdx.x >> 3;            // n' = j*1024 + d
    float* dst = (j == 0) ? g_u0 : (j == 1) ? g_g1 : g_g2;
    const int dl0 = (blockIdx.x & 7) * 128;
    const int r0 = bm + wm + (lane >> 2);
#pragma unroll
    for (int mt = 0; mt < 2; mt++) {
#pragma unroll
        for (int n8 = 0; n8 < 8; n8++) {
            const int col = dl0 + wn + n8 * 8 + (lane & 3) * 2;
            float b0 = 0.f, b1 = 0.f;
            if (j) { b0 = bias[(j-1)*1024 + col]; b1 = bias[(j-1)*1024 + col + 1]; }
            float v0 = acc[mt][n8][0], v1 = acc[mt][n8][1];
            float v2 = acc[mt][n8][2], v3 = acc[mt][n8][3];
            if (j) {
                v0 = __fdividef(1.f, 1.f + __expf(-(v0 + b0)));
                v1 = __fdividef(1.f, 1.f + __expf(-(v1 + b1)));
                v2 = __fdividef(1.f, 1.f + __expf(-(v2 + b0)));
                v3 = __fdividef(1.f, 1.f + __expf(-(v3 + b1)));
            }
            *(float2*)&dst[(size_t)(r0 + mt*16) * 1024 + col]     = make_float2(v0, v1);
            *(float2*)&dst[(size_t)(r0 + mt*16 + 8) * 1024 + col] = make_float2(v2, v3);
        }
    }
}

// ---------------- scan: c_l = (c - u0)*g1 + u0 ; h = (tanh(c)-x)*g2 + x
#define SG 8
__global__ void __launch_bounds__(256) scan_kernel(const float* __restrict__ x,
                                                   const float* __restrict__ c0,
                                                   float* __restrict__ h) {
    const int b = blockIdx.x >> 2;
    const int d = ((blockIdx.x & 3) << 8) + threadIdx.x;
    const size_t STEP = (size_t)B_DIM * D_DIM;     // 32768
    size_t off = (size_t)b * D_DIM + d;
    float c = c0[off];
    float cu[SG], cg[SG], ce[SG], cx[SG];
#pragma unroll
    for (int i = 0; i < SG; i++) {
        size_t o = off + i*STEP;
        cu[i] = g_u0[o]; cg[i] = g_g1[o]; ce[i] = g_g2[o]; cx[i] = x[o];
    }
#pragma unroll 1
    for (int g = 0; g < L_DIM/SG; g++) {
        float nu[SG], ng[SG], ne[SG], nx[SG];
        if (g < L_DIM/SG - 1) {
            size_t o2 = off + SG*STEP;
#pragma unroll
            for (int i = 0; i < SG; i++) {
                size_t o = o2 + i*STEP;
                nu[i] = g_u0[o]; ng[i] = g_g1[o]; ne[i] = g_g2[o]; nx[i] = x[o];
            }
        }
#pragma unroll
        for (int i = 0; i < SG; i++) {
            c = (c - cu[i]) * cg[i] + cu[i];
            float e = __expf(-2.f * c);
            float th = __fdividef(1.f - e, 1.f + e);
            h[off + i*STEP] = (th - cx[i]) * ce[i] + cx[i];
        }
        off += SG*STEP;
#pragma unroll
        for (int i = 0; i < SG; i++) { cu[i]=nu[i]; cg[i]=ng[i]; ce[i]=ne[i]; cx[i]=nx[i]; }
    }
}

// ---------------- launch ----------------
extern "C" void kernel_launch(void* const* d_in, const int* in_sizes, int n_in,
                              void* d_out, int out_size) {
    const float* x    = (const float*)d_in[0];
    const float* W    = (const float*)d_in[1];
    const float* bias = (const float*)d_in[2];
    const float* c0   = (const float*)d_in[3];
    float* out = (float*)d_out;

    static int smem_set = 0;
    if (!smem_set) {
        cudaFuncSetAttribute(gemm_kernel, cudaFuncAttributeMaxDynamicSharedMemorySize, GEMM_SMEM);
        smem_set = 1;
    }

    prepw_kernel<<<dim3(N_DIM/32, K_DIM/32), dim3(32, 8)>>>(W);
    prepx_kernel<<<(size_t)M_DIM*K_DIM/2048, 256>>>(x);
    gemm_kernel<<<dim3(N_DIM/BN, M_DIM/BM), 256, GEMM_SMEM>>>(bias);
    scan_kernel<<<(B_DIM*D_DIM)/256, 256>>>(x, c0, out);
}